// round 16
// baseline (speedup 1.0000x reference)
#include <cuda_runtime.h>
#include <cuda_fp16.h>
#include <cstdint>

#define NROWS 16384
#define KDIM  16384
#define NCOLS 64
#define KC    64
#define NCHUNK (KDIM / KC)
#define BSTRIDE ((KC * 2) / 16)   // uint4s per chunk of one B row = 8

// -------- device scratch --------
__device__ __align__(256) float  g_sup[(size_t)NROWS * NCOLS];
__device__ __align__(256) __half g_bh[(size_t)NCOLS * KDIM];   // support^T (fp16)

// -------- helpers --------
__device__ __forceinline__ uint32_t smem_u32(const void* p) {
    uint32_t a;
    asm("{ .reg .u64 t; cvta.to.shared.u64 t, %1; cvt.u32.u64 %0, t; }" : "=r"(a) : "l"(p));
    return a;
}
__device__ __forceinline__ uint32_t sw128(uint32_t off) { return off ^ ((off >> 3) & 0x70); }

__device__ __forceinline__ uint32_t pack2h(float a, float b) {   // a -> LOW half
    uint32_t r;
    asm("cvt.rn.f16x2.f32 %0, %1, %2;" : "=r"(r) : "f"(b), "f"(a));
    return r;
}
__device__ __forceinline__ void sts128(uint32_t addr, uint32_t a, uint32_t b, uint32_t c, uint32_t d) {
    asm volatile("st.shared.v4.b32 [%0], {%1,%2,%3,%4};"
                 :: "r"(addr), "r"(a), "r"(b), "r"(c), "r"(d) : "memory");
}
__device__ __forceinline__ void lds128f(uint32_t addr, float* v) {
    asm volatile("ld.shared.v4.f32 {%0,%1,%2,%3}, [%4];"
                 : "=f"(v[0]), "=f"(v[1]), "=f"(v[2]), "=f"(v[3]) : "r"(addr));
}
__device__ __forceinline__ void cp_async16(uint32_t saddr, const void* gaddr) {
    asm volatile("cp.async.cg.shared.global [%0], [%1], 16;"
                 :: "r"(saddr), "l"(gaddr) : "memory");
}
#define CP_COMMIT() asm volatile("cp.async.commit_group;" ::: "memory")
#define CP_WAIT1()  asm volatile("cp.async.wait_group 1;" ::: "memory")
#define CP_WAIT0()  asm volatile("cp.async.wait_group 0;" ::: "memory")

#define LDSM4(r, addr) \
    asm volatile("ldmatrix.sync.aligned.m8n8.x4.shared.b16 {%0,%1,%2,%3}, [%4];" \
                 : "=r"((r)[0]), "=r"((r)[1]), "=r"((r)[2]), "=r"((r)[3]) : "r"(addr))

#define MMAH(d, a, b0_, b1_) \
    asm volatile("mma.sync.aligned.m16n8k16.row.col.f32.f16.f16.f32 " \
                 "{%0,%1,%2,%3}, {%4,%5,%6,%7}, {%8,%9}, {%0,%1,%2,%3};" \
                 : "+f"((d)[0]), "+f"((d)[1]), "+f"((d)[2]), "+f"((d)[3]) \
                 : "r"((a)[0]), "r"((a)[1]), "r"((a)[2]), "r"((a)[3]), \
                   "r"(b0_), "r"(b1_))

// -------- prep: support = x @ W (smem-tiled) ; store fp32 + fp16 transposed plane --------
// 256 CTAs x 64 rows, 256 threads, 2 CTAs/SM. smem: x tile 64x64 (pitch 65) + W tile 64x64.
#define XS_PITCH 65
#define PREP_SMEM ((64 * XS_PITCH + 64 * 64) * 4)

__global__ __launch_bounds__(256, 2) void gcn_prep(const float* __restrict__ x,
                                                   const float* __restrict__ W) {
    extern __shared__ float psm[];
    float* xs = psm;                       // [64][65]
    float* ws = psm + 64 * XS_PITCH;       // [64][64]

    int tid = threadIdx.x;
    int rg = tid >> 3, cg = tid & 7;       // rg: 0..31 (2 rows each), cg: 0..7 (8 cols)
    int row0 = blockIdx.x * 64 + rg * 2;   // k dim of support^T (even)
    int c0 = cg * 8;                       // n dim
    float acc[2][8];
#pragma unroll
    for (int i = 0; i < 2; i++)
#pragma unroll
        for (int j = 0; j < 8; j++) acc[i][j] = 0.f;

    const float4* x4 = reinterpret_cast<const float4*>(x);   // row pitch 64 float4
    const float4* W4 = reinterpret_cast<const float4*>(W);   // row pitch 16 float4

    for (int kt = 0; kt < 4; kt++) {
        // stage x tile: 64 rows x 16 float4, fully coalesced
#pragma unroll
        for (int i = 0; i < 4; i++) {
            int lin = tid + i * 256;           // 0..1023
            int r = lin >> 4, c4 = lin & 15;
            float4 v = __ldg(&x4[(size_t)(blockIdx.x * 64 + r) * 64 + kt * 16 + c4]);
            float* dst = xs + r * XS_PITCH + c4 * 4;
            dst[0] = v.x; dst[1] = v.y; dst[2] = v.z; dst[3] = v.w;
        }
        // stage W tile: 64 rows x 16 float4
#pragma unroll
        for (int i = 0; i < 4; i++) {
            int lin = tid + i * 256;           // 0..1023
            int r = lin >> 4, c4 = lin & 15;
            float4 v = __ldg(&W4[(size_t)(kt * 64 + r) * 16 + c4]);
            reinterpret_cast<float4*>(ws)[r * 16 + c4] = v;
        }
        __syncthreads();

        const float* xrow0 = xs + (rg * 2 + 0) * XS_PITCH;
        const float* xrow1 = xs + (rg * 2 + 1) * XS_PITCH;
#pragma unroll 4
        for (int kk = 0; kk < 64; kk++) {
            float a0 = xrow0[kk], a1 = xrow1[kk];
            float4 wa = reinterpret_cast<const float4*>(ws)[kk * 16 + cg * 2];
            float4 wb = reinterpret_cast<const float4*>(ws)[kk * 16 + cg * 2 + 1];
            float av_[2] = {a0, a1};
#pragma unroll
            for (int i = 0; i < 2; i++) {
                acc[i][0] = fmaf(av_[i], wa.x, acc[i][0]);
                acc[i][1] = fmaf(av_[i], wa.y, acc[i][1]);
                acc[i][2] = fmaf(av_[i], wa.z, acc[i][2]);
                acc[i][3] = fmaf(av_[i], wa.w, acc[i][3]);
                acc[i][4] = fmaf(av_[i], wb.x, acc[i][4]);
                acc[i][5] = fmaf(av_[i], wb.y, acc[i][5]);
                acc[i][6] = fmaf(av_[i], wb.z, acc[i][6]);
                acc[i][7] = fmaf(av_[i], wb.w, acc[i][7]);
            }
        }
        __syncthreads();
    }

    // write-out (bit-identical layout/values to previous prep)
#pragma unroll
    for (int i = 0; i < 2; i++) {
        float* sp = g_sup + (size_t)(row0 + i) * NCOLS + c0;
        reinterpret_cast<float4*>(sp)[0] = make_float4(acc[i][0], acc[i][1], acc[i][2], acc[i][3]);
        reinterpret_cast<float4*>(sp)[1] = make_float4(acc[i][4], acc[i][5], acc[i][6], acc[i][7]);
    }
#pragma unroll
    for (int j = 0; j < 8; j++) {
        int n = c0 + j;
        uint32_t hv = pack2h(acc[0][j], acc[1][j]);
        *reinterpret_cast<uint32_t*>(g_bh + (size_t)n * KDIM + row0) = hv;
    }
}

// -------- main: out = relu(adj @ support + support + b) --------
// 256 CTAs x 64 rows, 256 threads, 2 CTAs/SM. Warp grid 2m x 2n x 2k; tile 32x32 on K/2.
// A: 2-stage smem + distance-2 reg ring. B: 4-stage smem via cp.async.cg (distance 2).
#define A_STAGE  8192
#define B_BASE   16384
#define B_STAGE  8192
#define SMEM_MAIN (1024 + 2 * A_STAGE + 4 * B_STAGE)

__device__ __forceinline__ void stage_A(uint32_t At, const float* f,
                                        uint32_t s0, uint32_t s1) {
    uint32_t h[8];
#pragma unroll
    for (int q = 0; q < 8; q++) h[q] = pack2h(f[2 * q], f[2 * q + 1]);
    sts128(At + s0, h[0], h[1], h[2], h[3]);
    sts128(At + s1, h[4], h[5], h[6], h[7]);
}

__global__ __launch_bounds__(256, 2) void gcn_main(const float* __restrict__ adj,
                                                   const float* __restrict__ bias,
                                                   float* __restrict__ out) {
    extern __shared__ char dsm[];
    uint32_t tiles = (smem_u32(dsm) + 1023) & ~1023u;
    int tid = threadIdx.x;
    int wid = tid >> 5;
    int lane = tid & 31;
    int row0 = blockIdx.x * 64;
    int wm = wid & 1, wn = (wid >> 1) & 1, wk = wid >> 2;

    // A loader: 64 rows x 4 segs of 16 floats -> 32B fp16
    int arow = tid >> 2, aseg = tid & 3;
    uint32_t a_s0 = sw128((uint32_t)arow * 128 + (uint32_t)aseg * 32);
    uint32_t a_s1 = sw128((uint32_t)arow * 128 + (uint32_t)aseg * 32 + 16);
    const float4* apbase = reinterpret_cast<const float4*>(
        adj + (size_t)(row0 + arow) * KDIM + aseg * 16);

    // B loader: 64 rows x 4 segs of 32B via cp.async (2x16B per thread)
    int bn = tid >> 2, bq = tid & 3;
    const uint4* bpbase = reinterpret_cast<const uint4*>(
        reinterpret_cast<const char*>(g_bh) + ((size_t)bn * KDIM) * 2 + (size_t)bq * 32);
    uint32_t b_s0 = sw128((uint32_t)bn * 128 + (uint32_t)bq * 32);
    uint32_t b_s1 = sw128((uint32_t)bn * 128 + (uint32_t)bq * 32 + 16);

    uint32_t Ast[2], Bst[4];
    Ast[0] = tiles;           Ast[1] = tiles + A_STAGE;
#pragma unroll
    for (int s = 0; s < 4; s++) Bst[s] = tiles + B_BASE + (uint32_t)s * B_STAGE;

#define CP_B(Bt, c) do { \
    const uint4* _s = bpbase + (size_t)(c) * BSTRIDE; \
    cp_async16((Bt) + b_s0, _s); \
    cp_async16((Bt) + b_s1, _s + 1); \
    CP_COMMIT(); \
} while (0)

    // fragment lane mappings
    uint32_t a_r = ((lane >> 3) & 1) * 8 + (lane & 7);
    uint32_t a_k = ((lane >> 4) & 1) * 16;
    uint32_t b_n = ((lane >> 4) & 1) * 8 + (lane & 7);
    uint32_t b_k = ((lane >> 3) & 1) * 16;
    uint32_t arowb[2], browb[2];
#pragma unroll
    for (int mt = 0; mt < 2; mt++) arowb[mt] = (wm * 32 + mt * 16 + a_r) * 128;
#pragma unroll
    for (int p = 0; p < 2; p++)   browb[p]  = (wn * 32 + p * 16 + b_n) * 128;

    float acc[2][4][4];
#pragma unroll
    for (int mt = 0; mt < 2; mt++)
#pragma unroll
        for (int nt = 0; nt < 4; nt++)
#pragma unroll
            for (int j = 0; j < 4; j++) acc[mt][nt][j] = 0.f;

#define MMA_CHUNK(At, Bt) do { \
    _Pragma("unroll") \
    for (int ks = 0; ks < 2; ks++) { \
        uint32_t ko = (uint32_t)wk * 64 + (uint32_t)(ks * 32); \
        uint32_t af[2][4], bf[2][4]; \
        _Pragma("unroll") \
        for (int mt = 0; mt < 2; mt++) \
            LDSM4(af[mt], (At) + sw128(arowb[mt] + ko + a_k)); \
        _Pragma("unroll") \
        for (int p = 0; p < 2; p++) \
            LDSM4(bf[p], (Bt) + sw128(browb[p] + ko + b_k)); \
        _Pragma("unroll") \
        for (int mt = 0; mt < 2; mt++) { \
            _Pragma("unroll") \
            for (int nt = 0; nt < 4; nt++) { \
                int p = nt >> 1, h = (nt & 1) * 2; \
                MMAH(acc[mt][nt], af[mt], bf[p][h], bf[p][h + 1]); \
            } \
        } \
    } \
} while (0)

    float av[2][16];

    // ---- prologue: B(0)->st0, B(1)->st1 async; A(0) staged; A(1) in regs ----
    {
        CP_B(Bst[0], 0);
        CP_B(Bst[1], 1);
#pragma unroll
        for (int q = 0; q < 4; q++)
            reinterpret_cast<float4*>(av[0])[q] = __ldcs(&apbase[q]);
        stage_A(Ast[0], av[0], a_s0, a_s1);
#pragma unroll
        for (int q = 0; q < 4; q++)
            reinterpret_cast<float4*>(av[1])[q] = __ldcs(&apbase[(size_t)(KC / 4) + q]);
        CP_WAIT1();   // B(0) done, B(1) may fly
    }
    __syncthreads();

    // ---- main loop: unroll x4; chunk c+h reads A stage (h&1), B stage h ----
#pragma unroll 1
    for (int c = 0; c < NCHUNK; c += 4) {
#define HALF(hh) do { \
        constexpr int h = (hh); \
        const bool ld_ok = (c + h + 2 < NCHUNK); \
        if (ld_ok) { \
            CP_B(Bst[(h + 2) & 3], c + h + 2); \
            const float4* ap = apbase + (size_t)(c + h + 2) * (KC / 4); \
            _Pragma("unroll") \
            for (int q = 0; q < 4; q++) \
                reinterpret_cast<float4*>(av[h & 1])[q] = __ldcs(&ap[q]); \
        } \
        MMA_CHUNK(Ast[h & 1], Bst[h]); \
        if (c + h + 1 < NCHUNK) \
            stage_A(Ast[(h + 1) & 1], av[(h + 1) & 1], a_s0, a_s1); \
        if (ld_ok) { CP_WAIT1(); } else { CP_WAIT0(); } \
        __syncthreads(); \
    } while (0)

        HALF(0);
        HALF(1);
        HALF(2);
        HALF(3);
#undef HALF
    }
#undef MMA_CHUNK
#undef CP_B

    // ---- merge k-split partials: wk=1 warps dump accs to smem ----
    if (wk == 1) {
#pragma unroll
        for (int mt = 0; mt < 2; mt++)
#pragma unroll
            for (int nt = 0; nt < 4; nt++) {
                uint32_t off = tiles + (uint32_t)(wid & 3) * 4096 +
                               (uint32_t)(mt * 4 + nt) * 512 + (uint32_t)lane * 16;
                sts128(off, __float_as_uint(acc[mt][nt][0]), __float_as_uint(acc[mt][nt][1]),
                             __float_as_uint(acc[mt][nt][2]), __float_as_uint(acc[mt][nt][3]));
            }
    }
    __syncthreads();

    // ---- epilogue (wk=0 warps): out = relu(acc + partial + support + bias) ----
    if (wk == 0) {
        int g = lane >> 2, t = lane & 3;
#pragma unroll
        for (int mt = 0; mt < 2; mt++) {
            int ra = row0 + wm * 32 + mt * 16 + g;
#pragma unroll
            for (int nt = 0; nt < 4; nt++) {
                float p[4];
                lds128f(tiles + (uint32_t)wid * 4096 + (uint32_t)(mt * 4 + nt) * 512 +
                        (uint32_t)lane * 16, p);
                int col = wn * 32 + nt * 8 + t * 2;
                float2 bb = *reinterpret_cast<const float2*>(bias + col);
                float2 s0 = *reinterpret_cast<const float2*>(g_sup + (size_t)ra * NCOLS + col);
                float2 s1 = *reinterpret_cast<const float2*>(g_sup + (size_t)(ra + 8) * NCOLS + col);
                float2 r0, r1;
                r0.x = fmaxf(acc[mt][nt][0] + p[0] + s0.x + bb.x, 0.f);
                r0.y = fmaxf(acc[mt][nt][1] + p[1] + s0.y + bb.y, 0.f);
                r1.x = fmaxf(acc[mt][nt][2] + p[2] + s1.x + bb.x, 0.f);
                r1.y = fmaxf(acc[mt][nt][3] + p[3] + s1.y + bb.y, 0.f);
                *reinterpret_cast<float2*>(out + (size_t)ra * NCOLS + col) = r0;
                *reinterpret_cast<float2*>(out + (size_t)(ra + 8) * NCOLS + col) = r1;
            }
        }
    }
}

extern "C" void kernel_launch(void* const* d_in, const int* in_sizes, int n_in,
                              void* d_out, int out_size) {
    const float *x = nullptr, *adj = nullptr, *W = nullptr, *b = nullptr;
    for (int i = 0; i < n_in; i++) {
        long s = in_sizes[i];
        if (s == (long)NROWS * 256)        x   = (const float*)d_in[i];
        else if (s == (long)NROWS * NROWS) adj = (const float*)d_in[i];
        else if (s == 256L * NCOLS)        W   = (const float*)d_in[i];
        else if (s == (long)NCOLS)         b   = (const float*)d_in[i];
    }
    cudaFuncSetAttribute(gcn_prep, cudaFuncAttributeMaxDynamicSharedMemorySize, PREP_SMEM);
    cudaFuncSetAttribute(gcn_main, cudaFuncAttributeMaxDynamicSharedMemorySize, SMEM_MAIN);
    gcn_prep<<<256, 256, PREP_SMEM>>>(x, W);
    gcn_main<<<256, 256, SMEM_MAIN>>>(adj, b, (float*)d_out);
}

// round 17
// speedup vs baseline: 1.1031x; 1.1031x over previous
#include <cuda_runtime.h>
#include <cuda_fp16.h>
#include <cstdint>

#define NROWS 16384
#define KDIM  16384
#define NCOLS 64
#define KC    64
#define NCHUNK (KDIM / KC)
#define BSTRIDE ((KC * 2) / 16)   // uint4s per chunk of one B row = 8

// -------- device scratch --------
__device__ __align__(256) float  g_sup[(size_t)NROWS * NCOLS];
__device__ __align__(256) __half g_bh[(size_t)NCOLS * KDIM];   // support^T (fp16)

// -------- helpers --------
__device__ __forceinline__ uint32_t smem_u32(const void* p) {
    uint32_t a;
    asm("{ .reg .u64 t; cvta.to.shared.u64 t, %1; cvt.u32.u64 %0, t; }" : "=r"(a) : "l"(p));
    return a;
}
__device__ __forceinline__ uint32_t sw128(uint32_t off) { return off ^ ((off >> 3) & 0x70); }

__device__ __forceinline__ uint32_t pack2h(float a, float b) {   // a -> LOW half
    uint32_t r;
    asm("cvt.rn.f16x2.f32 %0, %1, %2;" : "=r"(r) : "f"(b), "f"(a));
    return r;
}
__device__ __forceinline__ void sts128(uint32_t addr, uint32_t a, uint32_t b, uint32_t c, uint32_t d) {
    asm volatile("st.shared.v4.b32 [%0], {%1,%2,%3,%4};"
                 :: "r"(addr), "r"(a), "r"(b), "r"(c), "r"(d) : "memory");
}
__device__ __forceinline__ void lds128f(uint32_t addr, float* v) {
    asm volatile("ld.shared.v4.f32 {%0,%1,%2,%3}, [%4];"
                 : "=f"(v[0]), "=f"(v[1]), "=f"(v[2]), "=f"(v[3]) : "r"(addr));
}
__device__ __forceinline__ void cp_async16(uint32_t saddr, const void* gaddr) {
    asm volatile("cp.async.cg.shared.global [%0], [%1], 16;"
                 :: "r"(saddr), "l"(gaddr) : "memory");
}
#define CP_COMMIT() asm volatile("cp.async.commit_group;" ::: "memory")
#define CP_WAIT1()  asm volatile("cp.async.wait_group 1;" ::: "memory")
#define CP_WAIT0()  asm volatile("cp.async.wait_group 0;" ::: "memory")

#define LDSM4(r, addr) \
    asm volatile("ldmatrix.sync.aligned.m8n8.x4.shared.b16 {%0,%1,%2,%3}, [%4];" \
                 : "=r"((r)[0]), "=r"((r)[1]), "=r"((r)[2]), "=r"((r)[3]) : "r"(addr))

#define MMAH(d, a, b0_, b1_) \
    asm volatile("mma.sync.aligned.m16n8k16.row.col.f32.f16.f16.f32 " \
                 "{%0,%1,%2,%3}, {%4,%5,%6,%7}, {%8,%9}, {%0,%1,%2,%3};" \
                 : "+f"((d)[0]), "+f"((d)[1]), "+f"((d)[2]), "+f"((d)[3]) \
                 : "r"((a)[0]), "r"((a)[1]), "r"((a)[2]), "r"((a)[3]), \
                   "r"(b0_), "r"(b1_))

// ==================== prep: support = x @ W via tensor cores ====================
// 256 CTAs x 64 rows, 256 threads, 2 CTAs/SM. Warp grid 2m x 2n x 2k (same as main).
// A = x (fp32 -> fp16 hi/lo staged, 4 chunks of K=64). B = W^T resident in smem,
// hi/lo planes, main's B-tile format (n-major 128B rows, SW128).
// 3-product split: ah*bh + ah*bl + al*bh (dropped al*bl ~ 2^-24).
// smem: WT_H 32KB | WT_L 32KB | A stages 2 x (hi 8KB + lo 8KB) = 32KB -> 96KB
#define P_WT_H 0
#define P_WT_L 32768
#define P_AST  65536
#define PREP_SMEM (98304 + 1024)

__device__ __forceinline__ void stage_A2(uint32_t Ah, uint32_t Al, const float* f,
                                         uint32_t s0, uint32_t s1) {
    uint32_t h[8], l[8];
#pragma unroll
    for (int q = 0; q < 8; q++) {
        h[q] = pack2h(f[2 * q], f[2 * q + 1]);
        __half2 hh = *reinterpret_cast<__half2*>(&h[q]);
        float f0 = __low2float(hh), f1 = __high2float(hh);
        l[q] = pack2h(f[2 * q] - f0, f[2 * q + 1] - f1);
    }
    sts128(Ah + s0, h[0], h[1], h[2], h[3]);
    sts128(Ah + s1, h[4], h[5], h[6], h[7]);
    sts128(Al + s0, l[0], l[1], l[2], l[3]);
    sts128(Al + s1, l[4], l[5], l[6], l[7]);
}

__global__ __launch_bounds__(256, 2) void gcn_prep(const float* __restrict__ x,
                                                   const float* __restrict__ W) {
    extern __shared__ char dsm[];
    uint32_t tiles = (smem_u32(dsm) + 1023) & ~1023u;
    int tid = threadIdx.x;
    int wid = tid >> 5;
    int lane = tid & 31;
    int row0 = blockIdx.x * 64;
    int wm = wid & 1, wn = (wid >> 1) & 1, wk = wid >> 2;

    // ---- build W^T hi/lo tiles (once): W[k][n] -> wt[ch][n][kc] ----
#pragma unroll 4
    for (int i = 0; i < 64; i++) {
        int e = i * 256 + tid;            // 0..16383
        int k = e >> 6, n = e & 63;
        float w = __ldg(&W[e]);
        __half wh = __float2half_rn(w);
        __half wl = __float2half_rn(w - __half2float(wh));
        uint32_t off = (uint32_t)(k >> 6) * 8192 +
                       sw128((uint32_t)n * 128 + (uint32_t)(k & 63) * 2);
        *reinterpret_cast<__half*>(dsm + (tiles - smem_u32(dsm)) + P_WT_H + off) = wh;
        *reinterpret_cast<__half*>(dsm + (tiles - smem_u32(dsm)) + P_WT_L + off) = wl;
    }

    // A loader: 64 rows x 4 segs of 16 floats (x row pitch = 64 float4)
    int arow = tid >> 2, aseg = tid & 3;
    uint32_t a_s0 = sw128((uint32_t)arow * 128 + (uint32_t)aseg * 32);
    uint32_t a_s1 = sw128((uint32_t)arow * 128 + (uint32_t)aseg * 32 + 16);
    const float4* apbase = reinterpret_cast<const float4*>(
        x + (size_t)(row0 + arow) * 256 + aseg * 16);

    // fragment lane mappings (identical to main)
    uint32_t a_r = ((lane >> 3) & 1) * 8 + (lane & 7);
    uint32_t a_k = ((lane >> 4) & 1) * 16;
    uint32_t b_n = ((lane >> 4) & 1) * 8 + (lane & 7);
    uint32_t b_k = ((lane >> 3) & 1) * 16;
    uint32_t arowb[2], browb[2];
#pragma unroll
    for (int mt = 0; mt < 2; mt++) arowb[mt] = (wm * 32 + mt * 16 + a_r) * 128;
#pragma unroll
    for (int p = 0; p < 2; p++)   browb[p]  = (wn * 32 + p * 16 + b_n) * 128;

    float acc[2][4][4];
#pragma unroll
    for (int mt = 0; mt < 2; mt++)
#pragma unroll
        for (int nt = 0; nt < 4; nt++)
#pragma unroll
            for (int j = 0; j < 4; j++) acc[mt][nt][j] = 0.f;

    // ---- prologue: stage chunk 0 ----
    float av[16];
#pragma unroll
    for (int q = 0; q < 4; q++)
        reinterpret_cast<float4*>(av)[q] = __ldg(&apbase[q]);
    stage_A2(tiles + P_AST, tiles + P_AST + 8192, av, a_s0, a_s1);
    __syncthreads();

    // ---- 4 chunks of K=64 ----
#pragma unroll
    for (int c = 0; c < 4; c++) {
        int st = c & 1;
        uint32_t Ah = tiles + P_AST + (uint32_t)st * 16384;
        uint32_t Al = Ah + 8192;
        uint32_t Bh = tiles + P_WT_H + (uint32_t)c * 8192;
        uint32_t Bl = tiles + P_WT_L + (uint32_t)c * 8192;

        if (c + 1 < 4) {
#pragma unroll
            for (int q = 0; q < 4; q++)
                reinterpret_cast<float4*>(av)[q] = __ldg(&apbase[(size_t)(c + 1) * 16 + q]);
        }

#pragma unroll
        for (int ks = 0; ks < 2; ks++) {
            uint32_t ko = (uint32_t)wk * 64 + (uint32_t)(ks * 32);
            uint32_t afh[2][4], afl[2][4], bfh[2][4], bfl[2][4];
#pragma unroll
            for (int mt = 0; mt < 2; mt++) {
                LDSM4(afh[mt], Ah + sw128(arowb[mt] + ko + a_k));
                LDSM4(afl[mt], Al + sw128(arowb[mt] + ko + a_k));
            }
#pragma unroll
            for (int p = 0; p < 2; p++) {
                LDSM4(bfh[p], Bh + sw128(browb[p] + ko + b_k));
                LDSM4(bfl[p], Bl + sw128(browb[p] + ko + b_k));
            }
#pragma unroll
            for (int mt = 0; mt < 2; mt++) {
#pragma unroll
                for (int nt = 0; nt < 4; nt++) {
                    int p = nt >> 1, h = (nt & 1) * 2;
                    MMAH(acc[mt][nt], afh[mt], bfh[p][h], bfh[p][h + 1]);
                    MMAH(acc[mt][nt], afh[mt], bfl[p][h], bfl[p][h + 1]);
                    MMAH(acc[mt][nt], afl[mt], bfh[p][h], bfh[p][h + 1]);
                }
            }
        }

        if (c + 1 < 4) {
            uint32_t Ah2 = tiles + P_AST + (uint32_t)(st ^ 1) * 16384;
            stage_A2(Ah2, Ah2 + 8192, av, a_s0, a_s1);
        }
        __syncthreads();
    }

    // ---- merge k-split partials (reuse WT region as scratch) ----
    if (wk == 1) {
#pragma unroll
        for (int mt = 0; mt < 2; mt++)
#pragma unroll
            for (int nt = 0; nt < 4; nt++) {
                uint32_t off = tiles + (uint32_t)(wid & 3) * 4096 +
                               (uint32_t)(mt * 4 + nt) * 512 + (uint32_t)lane * 16;
                sts128(off, __float_as_uint(acc[mt][nt][0]), __float_as_uint(acc[mt][nt][1]),
                             __float_as_uint(acc[mt][nt][2]), __float_as_uint(acc[mt][nt][3]));
            }
    }
    __syncthreads();

    // ---- epilogue (wk=0): write g_sup fp32 + g_bh fp16 ----
    if (wk == 0) {
        int g = lane >> 2, t = lane & 3;
#pragma unroll
        for (int mt = 0; mt < 2; mt++) {
            int ra = row0 + wm * 32 + mt * 16 + g;
#pragma unroll
            for (int nt = 0; nt < 4; nt++) {
                float p[4];
                lds128f(tiles + (uint32_t)wid * 4096 + (uint32_t)(mt * 4 + nt) * 512 +
                        (uint32_t)lane * 16, p);
                int col = wn * 32 + nt * 8 + t * 2;
                float v0 = acc[mt][nt][0] + p[0];
                float v1 = acc[mt][nt][1] + p[1];
                float v2 = acc[mt][nt][2] + p[2];
                float v3 = acc[mt][nt][3] + p[3];
                *reinterpret_cast<float2*>(g_sup + (size_t)ra * NCOLS + col) = make_float2(v0, v1);
                *reinterpret_cast<float2*>(g_sup + (size_t)(ra + 8) * NCOLS + col) = make_float2(v2, v3);
                g_bh[(size_t)col * KDIM + ra]           = __float2half_rn(v0);
                g_bh[(size_t)(col + 1) * KDIM + ra]     = __float2half_rn(v1);
                g_bh[(size_t)col * KDIM + ra + 8]       = __float2half_rn(v2);
                g_bh[(size_t)(col + 1) * KDIM + ra + 8] = __float2half_rn(v3);
            }
        }
    }
}

// ==================== main: out = relu(adj @ support + support + b) ====================
// (byte-identical to the 248.6us R15 kernel)
#define A_STAGE  8192
#define B_BASE   16384
#define B_STAGE  8192
#define SMEM_MAIN (1024 + 2 * A_STAGE + 4 * B_STAGE)

__device__ __forceinline__ void stage_A(uint32_t At, const float* f,
                                        uint32_t s0, uint32_t s1) {
    uint32_t h[8];
#pragma unroll
    for (int q = 0; q < 8; q++) h[q] = pack2h(f[2 * q], f[2 * q + 1]);
    sts128(At + s0, h[0], h[1], h[2], h[3]);
    sts128(At + s1, h[4], h[5], h[6], h[7]);
}

__global__ __launch_bounds__(256, 2) void gcn_main(const float* __restrict__ adj,
                                                   const float* __restrict__ bias,
                                                   float* __restrict__ out) {
    extern __shared__ char dsm[];
    uint32_t tiles = (smem_u32(dsm) + 1023) & ~1023u;
    int tid = threadIdx.x;
    int wid = tid >> 5;
    int lane = tid & 31;
    int row0 = blockIdx.x * 64;
    int wm = wid & 1, wn = (wid >> 1) & 1, wk = wid >> 2;

    // A loader: 64 rows x 4 segs of 16 floats -> 32B fp16
    int arow = tid >> 2, aseg = tid & 3;
    uint32_t a_s0 = sw128((uint32_t)arow * 128 + (uint32_t)aseg * 32);
    uint32_t a_s1 = sw128((uint32_t)arow * 128 + (uint32_t)aseg * 32 + 16);
    const float4* apbase = reinterpret_cast<const float4*>(
        adj + (size_t)(row0 + arow) * KDIM + aseg * 16);

    // B loader: 64 rows x 4 segs of 32B via cp.async (2x16B per thread)
    int bn = tid >> 2, bq = tid & 3;
    const uint4* bpbase = reinterpret_cast<const uint4*>(
        reinterpret_cast<const char*>(g_bh) + ((size_t)bn * KDIM) * 2 + (size_t)bq * 32);
    uint32_t b_s0 = sw128((uint32_t)bn * 128 + (uint32_t)bq * 32);
    uint32_t b_s1 = sw128((uint32_t)bn * 128 + (uint32_t)bq * 32 + 16);

    uint32_t Ast[2], Bst[4];
    Ast[0] = tiles;           Ast[1] = tiles + A_STAGE;
#pragma unroll
    for (int s = 0; s < 4; s++) Bst[s] = tiles + B_BASE + (uint32_t)s * B_STAGE;

#define CP_B(Bt, c) do { \
    const uint4* _s = bpbase + (size_t)(c) * BSTRIDE; \
    cp_async16((Bt) + b_s0, _s); \
    cp_async16((Bt) + b_s1, _s + 1); \
    CP_COMMIT(); \
} while (0)

    // fragment lane mappings
    uint32_t a_r = ((lane >> 3) & 1) * 8 + (lane & 7);
    uint32_t a_k = ((lane >> 4) & 1) * 16;
    uint32_t b_n = ((lane >> 4) & 1) * 8 + (lane & 7);
    uint32_t b_k = ((lane >> 3) & 1) * 16;
    uint32_t arowb[2], browb[2];
#pragma unroll
    for (int mt = 0; mt < 2; mt++) arowb[mt] = (wm * 32 + mt * 16 + a_r) * 128;
#pragma unroll
    for (int p = 0; p < 2; p++)   browb[p]  = (wn * 32 + p * 16 + b_n) * 128;

    float acc[2][4][4];
#pragma unroll
    for (int mt = 0; mt < 2; mt++)
#pragma unroll
        for (int nt = 0; nt < 4; nt++)
#pragma unroll
            for (int j = 0; j < 4; j++) acc[mt][nt][j] = 0.f;

#define MMA_CHUNK(At, Bt) do { \
    _Pragma("unroll") \
    for (int ks = 0; ks < 2; ks++) { \
        uint32_t ko = (uint32_t)wk * 64 + (uint32_t)(ks * 32); \
        uint32_t af[2][4], bf[2][4]; \
        _Pragma("unroll") \
        for (int mt = 0; mt < 2; mt++) \
            LDSM4(af[mt], (At) + sw128(arowb[mt] + ko + a_k)); \
        _Pragma("unroll") \
        for (int p = 0; p < 2; p++) \
            LDSM4(bf[p], (Bt) + sw128(browb[p] + ko + b_k)); \
        _Pragma("unroll") \
        for (int mt = 0; mt < 2; mt++) { \
            _Pragma("unroll") \
            for (int nt = 0; nt < 4; nt++) { \
                int p = nt >> 1, h = (nt & 1) * 2; \
                MMAH(acc[mt][nt], af[mt], bf[p][h], bf[p][h + 1]); \
            } \
        } \
    } \
} while (0)

    float av[2][16];

    // ---- prologue: B(0)->st0, B(1)->st1 async; A(0) staged; A(1) in regs ----
    {
        CP_B(Bst[0], 0);
        CP_B(Bst[1], 1);
#pragma unroll
        for (int q = 0; q < 4; q++)
            reinterpret_cast<float4*>(av[0])[q] = __ldcs(&apbase[q]);
        stage_A(Ast[0], av[0], a_s0, a_s1);
#pragma unroll
        for (int q = 0; q < 4; q++)
            reinterpret_cast<float4*>(av[1])[q] = __ldcs(&apbase[(size_t)(KC / 4) + q]);
        CP_WAIT1();   // B(0) done, B(1) may fly
    }
    __syncthreads();

    // ---- main loop: unroll x4; chunk c+h reads A stage (h&1), B stage h ----
#pragma unroll 1
    for (int c = 0; c < NCHUNK; c += 4) {
#define HALF(hh) do { \
        constexpr int h = (hh); \
        const bool ld_ok = (c + h + 2 < NCHUNK); \
        if (ld_ok) { \
            CP_B(Bst[(h + 2) & 3], c + h + 2); \
            const float4* ap = apbase + (size_t)(c + h + 2) * (KC / 4); \
            _Pragma("unroll") \
            for (int q = 0; q < 4; q++) \
                reinterpret_cast<float4*>(av[h & 1])[q] = __ldcs(&ap[q]); \
        } \
        MMA_CHUNK(Ast[h & 1], Bst[h]); \
        if (c + h + 1 < NCHUNK) \
            stage_A(Ast[(h + 1) & 1], av[(h + 1) & 1], a_s0, a_s1); \
        if (ld_ok) { CP_WAIT1(); } else { CP_WAIT0(); } \
        __syncthreads(); \
    } while (0)

        HALF(0);
        HALF(1);
        HALF(2);
        HALF(3);
#undef HALF
    }
#undef MMA_CHUNK
#undef CP_B

    // ---- merge k-split partials: wk=1 warps dump accs to smem ----
    if (wk == 1) {
#pragma unroll
        for (int mt = 0; mt < 2; mt++)
#pragma unroll
            for (int nt = 0; nt < 4; nt++) {
                uint32_t off = tiles + (uint32_t)(wid & 3) * 4096 +
                               (uint32_t)(mt * 4 + nt) * 512 + (uint32_t)lane * 16;
                sts128(off, __float_as_uint(acc[mt][nt][0]), __float_as_uint(acc[mt][nt][1]),
                             __float_as_uint(acc[mt][nt][2]), __float_as_uint(acc[mt][nt][3]));
            }
    }
    __syncthreads();

    // ---- epilogue (wk=0 warps): out = relu(acc + partial + support + bias) ----
    if (wk == 0) {
        int g = lane >> 2, t = lane & 3;
#pragma unroll
        for (int mt = 0; mt < 2; mt++) {
            int ra = row0 + wm * 32 + mt * 16 + g;
#pragma unroll
            for (int nt = 0; nt < 4; nt++) {
                float p[4];
                lds128f(tiles + (uint32_t)wid * 4096 + (uint32_t)(mt * 4 + nt) * 512 +
                        (uint32_t)lane * 16, p);
                int col = wn * 32 + nt * 8 + t * 2;
                float2 bb = *reinterpret_cast<const float2*>(bias + col);
                float2 s0 = *reinterpret_cast<const float2*>(g_sup + (size_t)ra * NCOLS + col);
                float2 s1 = *reinterpret_cast<const float2*>(g_sup + (size_t)(ra + 8) * NCOLS + col);
                float2 r0, r1;
                r0.x = fmaxf(acc[mt][nt][0] + p[0] + s0.x + bb.x, 0.f);
                r0.y = fmaxf(acc[mt][nt][1] + p[1] + s0.y + bb.y, 0.f);
                r1.x = fmaxf(acc[mt][nt][2] + p[2] + s1.x + bb.x, 0.f);
                r1.y = fmaxf(acc[mt][nt][3] + p[3] + s1.y + bb.y, 0.f);
                *reinterpret_cast<float2*>(out + (size_t)ra * NCOLS + col) = r0;
                *reinterpret_cast<float2*>(out + (size_t)(ra + 8) * NCOLS + col) = r1;
            }
        }
    }
}

extern "C" void kernel_launch(void* const* d_in, const int* in_sizes, int n_in,
                              void* d_out, int out_size) {
    const float *x = nullptr, *adj = nullptr, *W = nullptr, *b = nullptr;
    for (int i = 0; i < n_in; i++) {
        long s = in_sizes[i];
        if (s == (long)NROWS * 256)        x   = (const float*)d_in[i];
        else if (s == (long)NROWS * NROWS) adj = (const float*)d_in[i];
        else if (s == 256L * NCOLS)        W   = (const float*)d_in[i];
        else if (s == (long)NCOLS)         b   = (const float*)d_in[i];
    }
    cudaFuncSetAttribute(gcn_prep, cudaFuncAttributeMaxDynamicSharedMemorySize, PREP_SMEM);
    cudaFuncSetAttribute(gcn_main, cudaFuncAttributeMaxDynamicSharedMemorySize, SMEM_MAIN);
    gcn_prep<<<256, 256, PREP_SMEM>>>(x, W);
    gcn_main<<<256, 256, SMEM_MAIN>>>(adj, b, (float*)d_out);
}